// round 1
// baseline (speedup 1.0000x reference)
#include <cuda_runtime.h>
#include <cstdint>

#define NN 50000   // nodes
#define NE 800000  // edges
#define DI 64      // in/out channels
#define DE 32      // edge attr dim
#define DH 128     // hidden dim
#define TE 64      // edge tile per block in K1

// ---------------- scratch (static device globals: no allocation) ----------------
__device__ float    g_messages[(size_t)NE * DI];  // 204.8 MB
__device__ float    g_scores[NE];
__device__ float    g_ex[NE];
__device__ unsigned g_segmax[NN];                 // order-preserving float encoding
__device__ float    g_denom[NN];

// monotonic float<->uint encoding so atomicMax(unsigned) == max(float)
__device__ __forceinline__ unsigned enc_f(float f) {
    unsigned u = __float_as_uint(f);
    return (u & 0x80000000u) ? ~u : (u | 0x80000000u);
}
__device__ __forceinline__ float dec_f(unsigned u) {
    return (u & 0x80000000u) ? __uint_as_float(u & 0x7FFFFFFFu)
                             : __uint_as_float(~u);
}

// ---------------- K0: zero output / denom / segmax ----------------
__global__ void k0_init(float* __restrict__ out) {
    int i = blockIdx.x * blockDim.x + threadIdx.x;
    if (i < NN * DI) out[i] = 0.f;
    if (i < NN) { g_segmax[i] = 0u; g_denom[i] = 0.f; }
}

// ---------------- K1: fused edge MLP + gather-multiply + scores + segmax ----------------
// Per block: 64 edges. GEMM1 [64,32]@[32,128] -> tanh -> GEMM2 [64,128]@[128,64]
// -> ew + b2 -> m = x[src]*ew -> store m, score = m . attn_v -> shuffle-reduce
// -> store score + atomicMax segment max.
__global__ void __launch_bounds__(256) k1_mlp(
    const float* __restrict__ x,  const int*   __restrict__ ei,
    const float* __restrict__ ea, const float* __restrict__ W1,
    const float* __restrict__ b1, const float* __restrict__ W2,
    const float* __restrict__ b2, const float* __restrict__ av)
{
    __shared__ float sEAT[DE][TE];   // edge_attr transposed: [32][64]  (8 KB)
    __shared__ float sH[TE][DH];     // hidden activations:   [64][128] (32 KB)
    __shared__ int   sSrc[TE];
    __shared__ int   sTgt[TE];

    const int t  = threadIdx.x;
    const int tx = t & 15;           // 16
    const int ty = t >> 4;           // 16
    const int e0 = blockIdx.x * TE;

    // stage edge_attr (transposed) : 64 edges x 32 = 512 float4, 2 per thread
    #pragma unroll
    for (int r = 0; r < 2; r++) {
        int idx = t + r * 256;
        int e = idx >> 3, q = idx & 7;
        float4 v = *reinterpret_cast<const float4*>(ea + (size_t)(e0 + e) * DE + q * 4);
        sEAT[q * 4 + 0][e] = v.x;
        sEAT[q * 4 + 1][e] = v.y;
        sEAT[q * 4 + 2][e] = v.z;
        sEAT[q * 4 + 3][e] = v.w;
    }
    if (t < TE) {
        sSrc[t] = ei[e0 + t];        // edge_index[0][e]
        sTgt[t] = ei[NE + e0 + t];   // edge_index[1][e]
    }
    __syncthreads();

    // ---- GEMM1: thread computes edges ty*4..+3, hidden cols tx*8..+7 ----
    float acc[4][8];
    #pragma unroll
    for (int i = 0; i < 4; i++)
        #pragma unroll
        for (int j = 0; j < 8; j++) acc[i][j] = 0.f;

    #pragma unroll 8
    for (int k = 0; k < DE; k++) {
        float4 a   = *reinterpret_cast<const float4*>(&sEAT[k][ty * 4]);
        float4 blo = __ldg(reinterpret_cast<const float4*>(W1 + k * DH + tx * 8));
        float4 bhi = __ldg(reinterpret_cast<const float4*>(W1 + k * DH + tx * 8 + 4));
        float aa[4] = {a.x, a.y, a.z, a.w};
        float bb[8] = {blo.x, blo.y, blo.z, blo.w, bhi.x, bhi.y, bhi.z, bhi.w};
        #pragma unroll
        for (int i = 0; i < 4; i++)
            #pragma unroll
            for (int j = 0; j < 8; j++)
                acc[i][j] = fmaf(aa[i], bb[j], acc[i][j]);
    }

    // bias + tanh -> shared H
    {
        float4 b1lo = __ldg(reinterpret_cast<const float4*>(b1 + tx * 8));
        float4 b1hi = __ldg(reinterpret_cast<const float4*>(b1 + tx * 8 + 4));
        float bb[8] = {b1lo.x, b1lo.y, b1lo.z, b1lo.w, b1hi.x, b1hi.y, b1hi.z, b1hi.w};
        #pragma unroll
        for (int i = 0; i < 4; i++)
            #pragma unroll
            for (int j = 0; j < 8; j++)
                sH[ty * 4 + i][tx * 8 + j] = tanhf(acc[i][j] + bb[j]);
    }
    __syncthreads();

    // ---- GEMM2: thread computes edges ty*4..+3, out cols tx*4..+3 ----
    float acc2[4][4];
    #pragma unroll
    for (int i = 0; i < 4; i++)
        #pragma unroll
        for (int j = 0; j < 4; j++) acc2[i][j] = 0.f;

    #pragma unroll 8
    for (int k = 0; k < DH; k++) {
        float a0 = sH[ty * 4 + 0][k];
        float a1 = sH[ty * 4 + 1][k];
        float a2 = sH[ty * 4 + 2][k];
        float a3 = sH[ty * 4 + 3][k];
        float4 b = __ldg(reinterpret_cast<const float4*>(W2 + k * DI + tx * 4));
        float bb[4] = {b.x, b.y, b.z, b.w};
        float aa[4] = {a0, a1, a2, a3};
        #pragma unroll
        for (int i = 0; i < 4; i++)
            #pragma unroll
            for (int j = 0; j < 4; j++)
                acc2[i][j] = fmaf(aa[i], bb[j], acc2[i][j]);
    }

    // ---- epilogue: ew = acc2 + b2 ; m = x[src] * ew ; score = m . v ----
    float4 b2v = __ldg(reinterpret_cast<const float4*>(b2 + tx * 4));
    float4 avv = __ldg(reinterpret_cast<const float4*>(av + tx * 4));

    float p[4];
    #pragma unroll
    for (int i = 0; i < 4; i++) {
        int le  = ty * 4 + i;
        int e   = e0 + le;
        int src = sSrc[le];
        float4 xv = __ldg(reinterpret_cast<const float4*>(x + (size_t)src * DI + tx * 4));
        float4 m;
        m.x = xv.x * (acc2[i][0] + b2v.x);
        m.y = xv.y * (acc2[i][1] + b2v.y);
        m.z = xv.z * (acc2[i][2] + b2v.z);
        m.w = xv.w * (acc2[i][3] + b2v.w);
        *reinterpret_cast<float4*>(g_messages + (size_t)e * DI + tx * 4) = m;
        p[i] = m.x * avv.x + m.y * avv.y + m.z * avv.z + m.w * avv.w;
    }

    // reduce score partials across the 16 tx lanes (xor offsets stay in half-warp)
    #pragma unroll
    for (int o = 1; o < 16; o <<= 1) {
        #pragma unroll
        for (int i = 0; i < 4; i++)
            p[i] += __shfl_xor_sync(0xFFFFFFFFu, p[i], o);
    }

    if (tx == 0) {
        #pragma unroll
        for (int i = 0; i < 4; i++) {
            int le = ty * 4 + i;
            int e  = e0 + le;
            g_scores[e] = p[i];
            atomicMax(&g_segmax[sTgt[le]], enc_f(p[i]));
        }
    }
}

// ---------------- K2: ex = exp(score - segmax[tgt]); denom accumulate ----------------
__global__ void k2_exp_denom(const int* __restrict__ ei) {
    int e = blockIdx.x * blockDim.x + threadIdx.x;
    if (e >= NE) return;
    int tgt = ei[NE + e];
    float ex = expf(g_scores[e] - dec_f(g_segmax[tgt]));
    g_ex[e] = ex;
    atomicAdd(&g_denom[tgt], ex);
}

// ---------------- K3: attention weights + weighted scatter-add ----------------
// one thread per (edge, 4-col group): 16 threads/edge, vector float4 reductions.
__global__ void k3_scatter(const int* __restrict__ ei,
                           float* __restrict__ out, float* __restrict__ att) {
    int t = blockIdx.x * blockDim.x + threadIdx.x;
    int e = t >> 4;
    if (e >= NE) return;
    int c   = (t & 15) << 2;
    int tgt = ei[NE + e];
    float aw = g_ex[e] / g_denom[tgt];
    if ((t & 15) == 0) att[e] = aw;
    float4 m = *reinterpret_cast<const float4*>(g_messages + (size_t)e * DI + c);
    float* addr = out + (size_t)tgt * DI + c;
    float v0 = m.x * aw, v1 = m.y * aw, v2 = m.z * aw, v3 = m.w * aw;
    asm volatile("red.global.add.v4.f32 [%0], {%1, %2, %3, %4};"
                 :: "l"(addr), "f"(v0), "f"(v1), "f"(v2), "f"(v3)
                 : "memory");
}

// ---------------- launch ----------------
extern "C" void kernel_launch(void* const* d_in, const int* in_sizes, int n_in,
                              void* d_out, int out_size) {
    const float* x  = (const float*)d_in[0];
    const int*   ei = (const int*)  d_in[1];
    const float* ea = (const float*)d_in[2];
    const float* W1 = (const float*)d_in[3];
    const float* b1 = (const float*)d_in[4];
    const float* W2 = (const float*)d_in[5];
    const float* b2 = (const float*)d_in[6];
    const float* av = (const float*)d_in[7];

    float* out = (float*)d_out;                 // [NN, DI]
    float* att = out + (size_t)NN * DI;         // [NE]

    k0_init<<<(NN * DI + 255) / 256, 256>>>(out);
    k1_mlp<<<NE / TE, 256>>>(x, ei, ea, W1, b1, W2, b2, av);
    k2_exp_denom<<<(NE + 255) / 256, 256>>>(ei);
    k3_scatter<<<(NE * 16 + 255) / 256, 256>>>(ei, out, att);
}

// round 5
// speedup vs baseline: 1.4829x; 1.4829x over previous
#include <cuda_runtime.h>
#include <cuda_bf16.h>
#include <cstdint>

#define NN 50000
#define NE 800000
#define DI 64
#define DE 32
#define DH 128
#define TE 128
#define NTILES (NE / TE)   // 6250

// row strides in BYTES
#define A_STRB  80     // bf16 edge tile rows
#define W1_STRB 272    // bf16 W1 rows (k-major)
#define W2_STRB 144    // bf16 W2 rows (k-major)
#define EW_STR  76     // f32 elements per row (304B)

// ---------------- scratch ----------------
__device__ float    g_messages[(size_t)NE * DI];
__device__ float    g_scores[NE];
__device__ float    g_ex[NE];
__device__ unsigned g_segmax[NN];
__device__ float    g_denom[NN];

__device__ __forceinline__ unsigned enc_f(float f) {
    unsigned u = __float_as_uint(f);
    return (u & 0x80000000u) ? ~u : (u | 0x80000000u);
}
__device__ __forceinline__ float dec_f(unsigned u) {
    return (u & 0x80000000u) ? __uint_as_float(u & 0x7FFFFFFFu)
                             : __uint_as_float(~u);
}

__device__ __forceinline__ uint32_t smem_u32(const void* p) {
    uint32_t a;
    asm("{ .reg .u64 t; cvta.to.shared.u64 t, %1; cvt.u32.u64 %0, t; }" : "=r"(a) : "l"(p));
    return a;
}
__device__ __forceinline__ uint32_t pk2(__nv_bfloat16 a, __nv_bfloat16 b) {
    __nv_bfloat162 t; t.x = a; t.y = b;
    return *reinterpret_cast<uint32_t*>(&t);
}
__device__ __forceinline__ uint32_t pk2f(float a, float b) {
    return pk2(__float2bfloat16_rn(a), __float2bfloat16_rn(b));
}
__device__ __forceinline__ float bl(float v) {          // lo residual
    return v - __bfloat162float(__float2bfloat16_rn(v));
}

#define LDSM_X4(r0, r1, r2, r3, addr) \
    asm volatile("ldmatrix.sync.aligned.m8n8.x4.shared.b16 {%0,%1,%2,%3}, [%4];" \
        : "=r"(r0), "=r"(r1), "=r"(r2), "=r"(r3) : "r"(addr))

#define LDSM_X2T(r0, r1, addr) \
    asm volatile("ldmatrix.sync.aligned.m8n8.x2.trans.shared.b16 {%0,%1}, [%2];" \
        : "=r"(r0), "=r"(r1) : "r"(addr))

#define MMA16816(d, a0, a1, a2, a3, b0, b1) \
    asm volatile("mma.sync.aligned.m16n8k16.row.col.f32.bf16.bf16.f32 " \
        "{%0,%1,%2,%3}, {%4,%5,%6,%7}, {%8,%9}, {%0,%1,%2,%3};" \
        : "+f"((d)[0]), "+f"((d)[1]), "+f"((d)[2]), "+f"((d)[3]) \
        : "r"(a0), "r"(a1), "r"(a2), "r"(a3), "r"(b0), "r"(b1))

// ---- smem layout (bytes) ----
#define S_SRC   0
#define S_TGT   512
#define S_B1    1024
#define S_B2    1536
#define S_AV    1792
#define S_AH    2048        // 128 x 80B  = 10240
#define S_AL    12288
#define S_W1H   22528       // 32 x 272B  = 8704
#define S_W1L   31232
#define S_W2H   39936       // 128 x 144B = 18432
#define S_W2L   58368
#define S_EW    76800       // 128 x 304B = 38912
#define S_TOTAL 115712

// ---------------- K0 ----------------
__global__ void k0_init(float* __restrict__ out) {
    int i = blockIdx.x * blockDim.x + threadIdx.x;
    if (i < NN * DI) out[i] = 0.f;
    if (i < NN) { g_segmax[i] = 0u; g_denom[i] = 0.f; }
}

// ---------------- K1: persistent mma.sync bf16x3, register-reuse H ----------------
__global__ void __launch_bounds__(256, 1) k1_mma(
    const float* __restrict__ x,  const int*   __restrict__ ei,
    const float* __restrict__ ea, const float* __restrict__ W1,
    const float* __restrict__ b1, const float* __restrict__ W2,
    const float* __restrict__ b2, const float* __restrict__ av)
{
    extern __shared__ char smem[];
    const uint32_t sb = smem_u32(smem);
    const int tid = threadIdx.x;
    const int wid = tid >> 5;
    const int lid = tid & 31;
    const int rw  = wid * 16;            // this warp's 16 edge rows

    float* sf   = reinterpret_cast<float*>(smem);
    int*   sSrc = reinterpret_cast<int*>(smem + S_SRC);
    int*   sTgt = reinterpret_cast<int*>(smem + S_TGT);
    float* sB1  = sf + (S_B1 >> 2);
    float* sB2  = sf + (S_B2 >> 2);
    float* sAV  = sf + (S_AV >> 2);
    float* sEW  = sf + (S_EW >> 2);

    // ---- one-time: biases + weight hi/lo split ----
    if (tid < DH) sB1[tid] = b1[tid];
    if (tid < DI) { sB2[tid] = b2[tid]; sAV[tid] = av[tid]; }

    for (int idx = tid; idx < DE * DH; idx += 256) {            // W1 [32][128]
        int k = idx >> 7, n = idx & 127;
        float v = __ldg(W1 + k * DH + n);
        __nv_bfloat16 h = __float2bfloat16_rn(v);
        __nv_bfloat16 l = __float2bfloat16_rn(v - __bfloat162float(h));
        *reinterpret_cast<__nv_bfloat16*>(smem + S_W1H + k * W1_STRB + n * 2) = h;
        *reinterpret_cast<__nv_bfloat16*>(smem + S_W1L + k * W1_STRB + n * 2) = l;
    }
    for (int idx = tid; idx < DH * DI; idx += 256) {            // W2 [128][64]
        int k = idx >> 6, n = idx & 63;
        float v = __ldg(W2 + k * DI + n);
        __nv_bfloat16 h = __float2bfloat16_rn(v);
        __nv_bfloat16 l = __float2bfloat16_rn(v - __bfloat162float(h));
        *reinterpret_cast<__nv_bfloat16*>(smem + S_W2H + k * W2_STRB + n * 2) = h;
        *reinterpret_cast<__nv_bfloat16*>(smem + S_W2L + k * W2_STRB + n * 2) = l;
    }
    __syncthreads();

    for (int tile = blockIdx.x; tile < NTILES; tile += gridDim.x) {
        const int e0 = tile * TE;

        // ---- load + split edge tile (bf16 hi/lo) ----
        #pragma unroll
        for (int i = 0; i < 4; i++) {
            int idx4 = tid + i * 256;            // e = idx4>>3, q = idx4&7
            int e = idx4 >> 3, q = idx4 & 7;
            float4 v = __ldg(reinterpret_cast<const float4*>(ea + (size_t)(e0 + e) * DE + q * 4));
            uint2 hv = {pk2f(v.x, v.y), pk2f(v.z, v.w)};
            uint2 lv = {pk2f(bl(v.x), bl(v.y)), pk2f(bl(v.z), bl(v.w))};
            *reinterpret_cast<uint2*>(smem + S_AH + e * A_STRB + q * 8) = hv;
            *reinterpret_cast<uint2*>(smem + S_AL + e * A_STRB + q * 8) = lv;
        }
        if (tid < TE) {
            sSrc[tid] = ei[e0 + tid];
            sTgt[tid] = ei[NE + e0 + tid];
        }
        __syncthreads();

        // ---- GEMM1: each warp computes rows rw..rw+15 x ALL 128 cols ----
        float acc1[16][4];
        #pragma unroll
        for (int nt = 0; nt < 16; nt++)
            #pragma unroll
            for (int i = 0; i < 4; i++) acc1[nt][i] = 0.f;

        #pragma unroll
        for (int ks = 0; ks < 2; ks++) {
            uint32_t ah0, ah1, ah2, ah3, al0, al1, al2, al3;
            uint32_t aoff = (uint32_t)((rw + (lid & 15)) * A_STRB + ks * 32 + (lid >> 4) * 16);
            LDSM_X4(ah0, ah1, ah2, ah3, sb + S_AH + aoff);
            LDSM_X4(al0, al1, al2, al3, sb + S_AL + aoff);
            #pragma unroll
            for (int nt = 0; nt < 16; nt++) {
                uint32_t koff = (uint32_t)((ks * 16 + (lid & 15)) * W1_STRB + nt * 16);
                uint32_t bh0, bh1, bl0, bl1;
                LDSM_X2T(bh0, bh1, sb + S_W1H + koff);
                LDSM_X2T(bl0, bl1, sb + S_W1L + koff);
                MMA16816(acc1[nt], ah0, ah1, ah2, ah3, bh0, bh1);
                MMA16816(acc1[nt], al0, al1, al2, al3, bh0, bh1);
                MMA16816(acc1[nt], ah0, ah1, ah2, ah3, bl0, bl1);
            }
        }

        // ---- tanh(acc1 + b1) -> bf16 hi/lo A-fragments (in registers!) ----
        // D-fragment (row lid>>2/+8, col (lid&3)*2,+1) == A-fragment layout.
        uint32_t hiA[16][2], loA[16][2];
        #pragma unroll
        for (int nt = 0; nt < 16; nt++) {
            int c0 = nt * 8 + (lid & 3) * 2;
            float bb0 = sB1[c0], bb1 = sB1[c0 + 1];
            float t0 = tanhf(acc1[nt][0] + bb0);
            float t1 = tanhf(acc1[nt][1] + bb1);
            float t2 = tanhf(acc1[nt][2] + bb0);
            float t3 = tanhf(acc1[nt][3] + bb1);
            hiA[nt][0] = pk2f(t0, t1);
            hiA[nt][1] = pk2f(t2, t3);
            loA[nt][0] = pk2f(bl(t0), bl(t1));
            loA[nt][1] = pk2f(bl(t2), bl(t3));
        }

        // ---- GEMM2: rows rw..rw+15 x 64 cols, A from registers ----
        float acc2[8][4];
        #pragma unroll
        for (int nt = 0; nt < 8; nt++)
            #pragma unroll
            for (int i = 0; i < 4; i++) acc2[nt][i] = 0.f;

        #pragma unroll
        for (int ks = 0; ks < 8; ks++) {
            uint32_t ah0 = hiA[2 * ks][0],     ah1 = hiA[2 * ks][1];
            uint32_t ah2 = hiA[2 * ks + 1][0], ah3 = hiA[2 * ks + 1][1];
            uint32_t al0 = loA[2 * ks][0],     al1 = loA[2 * ks][1];
            uint32_t al2 = loA[2 * ks + 1][0], al3 = loA[2 * ks + 1][1];
            #pragma unroll
            for (int nt = 0; nt < 8; nt++) {
                uint32_t koff = (uint32_t)((ks * 16 + (lid & 15)) * W2_STRB + nt * 16);
                uint32_t bh0, bh1, bl0, bl1;
                LDSM_X2T(bh0, bh1, sb + S_W2H + koff);
                LDSM_X2T(bl0, bl1, sb + S_W2L + koff);
                MMA16816(acc2[nt], ah0, ah1, ah2, ah3, bh0, bh1);
                MMA16816(acc2[nt], al0, al1, al2, al3, bh0, bh1);
                MMA16816(acc2[nt], ah0, ah1, ah2, ah3, bl0, bl1);
            }
        }

        // ---- store ew = acc2 + b2 into sEW ----
        #pragma unroll
        for (int nt = 0; nt < 8; nt++) {
            int r0 = rw + (lid >> 2);
            int c0 = nt * 8 + (lid & 3) * 2;
            float bb0 = sB2[c0], bb1 = sB2[c0 + 1];
            float2 v0 = {acc2[nt][0] + bb0, acc2[nt][1] + bb1};
            float2 v1 = {acc2[nt][2] + bb0, acc2[nt][3] + bb1};
            *reinterpret_cast<float2*>(sEW + r0 * EW_STR + c0) = v0;
            *reinterpret_cast<float2*>(sEW + (r0 + 8) * EW_STR + c0) = v1;
        }
        __syncthreads();

        // ---- epilogue: m = x[src]*ew (in place); score dot; atomicMax ----
        {
            int r = tid >> 1, half = tid & 1;
            int src = sSrc[r];
            const float* xrow = x + (size_t)src * DI + half * 32;
            float* ewrow = sEW + r * EW_STR + half * 32;
            const float* avh = sAV + half * 32;
            float part = 0.f;
            #pragma unroll
            for (int j = 0; j < 8; j++) {
                float4 ew = *reinterpret_cast<const float4*>(ewrow + j * 4);
                float4 xv = __ldg(reinterpret_cast<const float4*>(xrow + j * 4));
                float4 m;
                m.x = xv.x * ew.x; m.y = xv.y * ew.y;
                m.z = xv.z * ew.z; m.w = xv.w * ew.w;
                *reinterpret_cast<float4*>(ewrow + j * 4) = m;
                float4 vv = *reinterpret_cast<const float4*>(avh + j * 4);
                part += m.x * vv.x + m.y * vv.y + m.z * vv.z + m.w * vv.w;
            }
            part += __shfl_xor_sync(0xFFFFFFFFu, part, 1);
            if (half == 0) {
                g_scores[e0 + r] = part;
                atomicMax(&g_segmax[sTgt[r]], enc_f(part));
            }
        }
        __syncthreads();

        // ---- coalesced message copy-out (32 KB) ----
        #pragma unroll
        for (int i = 0; i < 8; i++) {
            int idx4 = tid + i * 256;            // e = idx4>>4, q = idx4&15
            int e = idx4 >> 4, q = idx4 & 15;
            float4 v = *reinterpret_cast<const float4*>(sEW + e * EW_STR + q * 4);
            *reinterpret_cast<float4*>(g_messages + (size_t)(e0 + e) * DI + q * 4) = v;
        }
        __syncthreads();
    }
}

// ---------------- K2 ----------------
__global__ void k2_exp_denom(const int* __restrict__ ei) {
    int e = blockIdx.x * blockDim.x + threadIdx.x;
    if (e >= NE) return;
    int tgt = ei[NE + e];
    float ex = expf(g_scores[e] - dec_f(g_segmax[tgt]));
    g_ex[e] = ex;
    atomicAdd(&g_denom[tgt], ex);
}

// ---------------- K3 ----------------
__global__ void k3_scatter(const int* __restrict__ ei,
                           float* __restrict__ out, float* __restrict__ att) {
    int t = blockIdx.x * blockDim.x + threadIdx.x;
    int e = t >> 4;
    if (e >= NE) return;
    int c   = (t & 15) << 2;
    int tgt = ei[NE + e];
    float aw = g_ex[e] / g_denom[tgt];
    if ((t & 15) == 0) att[e] = aw;
    float4 m = *reinterpret_cast<const float4*>(g_messages + (size_t)e * DI + c);
    float* addr = out + (size_t)tgt * DI + c;
    float v0 = m.x * aw, v1 = m.y * aw, v2 = m.z * aw, v3 = m.w * aw;
    asm volatile("red.global.add.v4.f32 [%0], {%1, %2, %3, %4};"
                 :: "l"(addr), "f"(v0), "f"(v1), "f"(v2), "f"(v3) : "memory");
}

// ---------------- launch ----------------
extern "C" void kernel_launch(void* const* d_in, const int* in_sizes, int n_in,
                              void* d_out, int out_size) {
    const float* x  = (const float*)d_in[0];
    const int*   ei = (const int*)  d_in[1];
    const float* ea = (const float*)d_in[2];
    const float* W1 = (const float*)d_in[3];
    const float* b1 = (const float*)d_in[4];
    const float* W2 = (const float*)d_in[5];
    const float* b2 = (const float*)d_in[6];
    const float* av = (const float*)d_in[7];

    float* out = (float*)d_out;
    float* att = out + (size_t)NN * DI;

    cudaFuncSetAttribute(k1_mma, cudaFuncAttributeMaxDynamicSharedMemorySize, S_TOTAL);

    k0_init<<<(NN * DI + 255) / 256, 256>>>(out);
    k1_mma<<<148, 256, S_TOTAL>>>(x, ei, ea, W1, b1, W2, b2, av);
    k2_exp_denom<<<(NE + 255) / 256, 256>>>(ei);
    k3_scatter<<<(NE * 16 + 255) / 256, 256>>>(ei, out, att);
}

// round 6
// speedup vs baseline: 1.7436x; 1.1758x over previous
#include <cuda_runtime.h>
#include <cuda_bf16.h>
#include <cstdint>

#define NN 50000
#define NE 800000
#define DI 64
#define DE 32
#define DH 128
#define TE 128
#define NTILES (NE / TE)   // 6250

// row strides in BYTES
#define A_STRB  80     // bf16 edge tile rows
#define W1_STRB 272    // bf16 W1 rows (k-major)
#define W2_STRB 144    // bf16 W2 rows (k-major)
#define EW_STR  76     // f32 elements per row (304B)

// ---------------- scratch ----------------
__device__ float    g_messages[(size_t)NE * DI];
__device__ float    g_scores[NE];
__device__ float    g_ex[NE];
__device__ unsigned g_segmax[NN];
__device__ float    g_denom[NN];

__device__ __forceinline__ unsigned enc_f(float f) {
    unsigned u = __float_as_uint(f);
    return (u & 0x80000000u) ? ~u : (u | 0x80000000u);
}
__device__ __forceinline__ float dec_f(unsigned u) {
    return (u & 0x80000000u) ? __uint_as_float(u & 0x7FFFFFFFu)
                             : __uint_as_float(~u);
}

__device__ __forceinline__ uint32_t smem_u32(const void* p) {
    uint32_t a;
    asm("{ .reg .u64 t; cvta.to.shared.u64 t, %1; cvt.u32.u64 %0, t; }" : "=r"(a) : "l"(p));
    return a;
}
__device__ __forceinline__ uint32_t pk2(__nv_bfloat16 a, __nv_bfloat16 b) {
    __nv_bfloat162 t; t.x = a; t.y = b;
    return *reinterpret_cast<uint32_t*>(&t);
}
__device__ __forceinline__ uint32_t pk2f(float a, float b) {
    return pk2(__float2bfloat16_rn(a), __float2bfloat16_rn(b));
}
__device__ __forceinline__ float bl(float v) {          // lo residual
    return v - __bfloat162float(__float2bfloat16_rn(v));
}
__device__ __forceinline__ float tanh_fast(float v) {
    v = fminf(fmaxf(v, -20.f), 20.f);
    float e = __expf(2.f * v);
    return 1.f - __fdividef(2.f, e + 1.f);
}

#define LDSM_X4(r0, r1, r2, r3, addr) \
    asm volatile("ldmatrix.sync.aligned.m8n8.x4.shared.b16 {%0,%1,%2,%3}, [%4];" \
        : "=r"(r0), "=r"(r1), "=r"(r2), "=r"(r3) : "r"(addr))

#define LDSM_X4T(r0, r1, r2, r3, addr) \
    asm volatile("ldmatrix.sync.aligned.m8n8.x4.trans.shared.b16 {%0,%1,%2,%3}, [%4];" \
        : "=r"(r0), "=r"(r1), "=r"(r2), "=r"(r3) : "r"(addr))

#define MMA16816(d, a0, a1, a2, a3, b0, b1) \
    asm volatile("mma.sync.aligned.m16n8k16.row.col.f32.bf16.bf16.f32 " \
        "{%0,%1,%2,%3}, {%4,%5,%6,%7}, {%8,%9}, {%0,%1,%2,%3};" \
        : "+f"((d)[0]), "+f"((d)[1]), "+f"((d)[2]), "+f"((d)[3]) \
        : "r"(a0), "r"(a1), "r"(a2), "r"(a3), "r"(b0), "r"(b1))

// ---- smem layout (bytes) ----
#define S_SRC   0
#define S_TGT   512
#define S_B1    1024
#define S_B2    1536
#define S_AV    1792
#define S_AH    2048        // 128 x 80B  = 10240
#define S_AL    12288
#define S_W1H   22528       // 32 x 272B  = 8704
#define S_W1L   31232
#define S_W2H   39936       // 128 x 144B = 18432
#define S_W2L   58368
#define S_EW    76800       // 128 x 304B = 38912
#define S_TOTAL 115712

// ---------------- K0 ----------------
__global__ void k0_init(float* __restrict__ out) {
    int i = blockIdx.x * blockDim.x + threadIdx.x;
    if (i < NN * DI) out[i] = 0.f;
    if (i < NN) { g_segmax[i] = 0u; g_denom[i] = 0.f; }
}

// ---------------- K1: persistent mma.sync bf16x3, register-reuse H ----------------
__global__ void __launch_bounds__(256, 1) k1_mma(
    const float* __restrict__ x,  const int*   __restrict__ ei,
    const float* __restrict__ ea, const float* __restrict__ W1,
    const float* __restrict__ b1, const float* __restrict__ W2,
    const float* __restrict__ b2, const float* __restrict__ av)
{
    extern __shared__ char smem[];
    const uint32_t sb = smem_u32(smem);
    const int tid = threadIdx.x;
    const int wid = tid >> 5;
    const int lid = tid & 31;
    const int rw  = wid * 16;            // this warp's 16 edge rows

    float* sf   = reinterpret_cast<float*>(smem);
    int*   sSrc = reinterpret_cast<int*>(smem + S_SRC);
    int*   sTgt = reinterpret_cast<int*>(smem + S_TGT);
    float* sB1  = sf + (S_B1 >> 2);
    float* sB2  = sf + (S_B2 >> 2);
    float* sAV  = sf + (S_AV >> 2);
    float* sEW  = sf + (S_EW >> 2);

    // ---- one-time: biases + weight hi/lo split ----
    if (tid < DH) sB1[tid] = b1[tid];
    if (tid < DI) { sB2[tid] = b2[tid]; sAV[tid] = av[tid]; }

    for (int idx = tid; idx < DE * DH; idx += 256) {            // W1 [32][128]
        int k = idx >> 7, n = idx & 127;
        float v = __ldg(W1 + k * DH + n);
        __nv_bfloat16 h = __float2bfloat16_rn(v);
        __nv_bfloat16 l = __float2bfloat16_rn(v - __bfloat162float(h));
        *reinterpret_cast<__nv_bfloat16*>(smem + S_W1H + k * W1_STRB + n * 2) = h;
        *reinterpret_cast<__nv_bfloat16*>(smem + S_W1L + k * W1_STRB + n * 2) = l;
    }
    for (int idx = tid; idx < DH * DI; idx += 256) {            // W2 [128][64]
        int k = idx >> 6, n = idx & 63;
        float v = __ldg(W2 + k * DI + n);
        __nv_bfloat16 h = __float2bfloat16_rn(v);
        __nv_bfloat16 l = __float2bfloat16_rn(v - __bfloat162float(h));
        *reinterpret_cast<__nv_bfloat16*>(smem + S_W2H + k * W2_STRB + n * 2) = h;
        *reinterpret_cast<__nv_bfloat16*>(smem + S_W2L + k * W2_STRB + n * 2) = l;
    }
    __syncthreads();

    for (int tile = blockIdx.x; tile < NTILES; tile += gridDim.x) {
        const int e0 = tile * TE;

        // ---- load + split edge tile (bf16 hi/lo) ----
        #pragma unroll
        for (int i = 0; i < 4; i++) {
            int idx4 = tid + i * 256;            // e = idx4>>3, q = idx4&7
            int e = idx4 >> 3, q = idx4 & 7;
            float4 v = __ldg(reinterpret_cast<const float4*>(ea + (size_t)(e0 + e) * DE + q * 4));
            uint2 hv = {pk2f(v.x, v.y), pk2f(v.z, v.w)};
            uint2 lv = {pk2f(bl(v.x), bl(v.y)), pk2f(bl(v.z), bl(v.w))};
            *reinterpret_cast<uint2*>(smem + S_AH + e * A_STRB + q * 8) = hv;
            *reinterpret_cast<uint2*>(smem + S_AL + e * A_STRB + q * 8) = lv;
        }
        if (tid < TE) {
            sSrc[tid] = ei[e0 + tid];
            sTgt[tid] = ei[NE + e0 + tid];
        }
        __syncthreads();

        // ---- GEMM1: each warp computes rows rw..rw+15 x ALL 128 cols ----
        float acc1[16][4];
        #pragma unroll
        for (int nt = 0; nt < 16; nt++)
            #pragma unroll
            for (int i = 0; i < 4; i++) acc1[nt][i] = 0.f;

        #pragma unroll
        for (int ks = 0; ks < 2; ks++) {
            uint32_t ah0, ah1, ah2, ah3, al0, al1, al2, al3;
            uint32_t aoff = (uint32_t)((rw + (lid & 15)) * A_STRB + ks * 32 + (lid >> 4) * 16);
            LDSM_X4(ah0, ah1, ah2, ah3, sb + S_AH + aoff);
            LDSM_X4(al0, al1, al2, al3, sb + S_AL + aoff);
            #pragma unroll
            for (int nt2 = 0; nt2 < 8; nt2++) {
                // x4.trans: lanes 0-15 -> cols nt2*16..+7 (nt=2*nt2), lanes 16-31 -> +8 (nt=2*nt2+1)
                uint32_t koff = (uint32_t)((ks * 16 + (lid & 15)) * W1_STRB
                                           + (nt2 * 16 + (lid >> 4) * 8) * 2);
                uint32_t bh0, bh1, bh2, bh3, bl0, bl1, bl2, bl3;
                LDSM_X4T(bh0, bh1, bh2, bh3, sb + S_W1H + koff);
                LDSM_X4T(bl0, bl1, bl2, bl3, sb + S_W1L + koff);
                MMA16816(acc1[2 * nt2],     ah0, ah1, ah2, ah3, bh0, bh1);
                MMA16816(acc1[2 * nt2],     al0, al1, al2, al3, bh0, bh1);
                MMA16816(acc1[2 * nt2],     ah0, ah1, ah2, ah3, bl0, bl1);
                MMA16816(acc1[2 * nt2 + 1], ah0, ah1, ah2, ah3, bh2, bh3);
                MMA16816(acc1[2 * nt2 + 1], al0, al1, al2, al3, bh2, bh3);
                MMA16816(acc1[2 * nt2 + 1], ah0, ah1, ah2, ah3, bl2, bl3);
            }
        }

        // ---- tanh(acc1 + b1) -> bf16 hi/lo A-fragments (in registers) ----
        uint32_t hiA[16][2], loA[16][2];
        #pragma unroll
        for (int nt = 0; nt < 16; nt++) {
            int c0 = nt * 8 + (lid & 3) * 2;
            float bb0 = sB1[c0], bb1 = sB1[c0 + 1];
            float t0 = tanh_fast(acc1[nt][0] + bb0);
            float t1 = tanh_fast(acc1[nt][1] + bb1);
            float t2 = tanh_fast(acc1[nt][2] + bb0);
            float t3 = tanh_fast(acc1[nt][3] + bb1);
            hiA[nt][0] = pk2f(t0, t1);
            hiA[nt][1] = pk2f(t2, t3);
            loA[nt][0] = pk2f(bl(t0), bl(t1));
            loA[nt][1] = pk2f(bl(t2), bl(t3));
        }

        // ---- GEMM2: rows rw..rw+15 x 64 cols, A from registers ----
        float acc2[8][4];
        #pragma unroll
        for (int nt = 0; nt < 8; nt++)
            #pragma unroll
            for (int i = 0; i < 4; i++) acc2[nt][i] = 0.f;

        #pragma unroll
        for (int ks = 0; ks < 8; ks++) {
            uint32_t ah0 = hiA[2 * ks][0],     ah1 = hiA[2 * ks][1];
            uint32_t ah2 = hiA[2 * ks + 1][0], ah3 = hiA[2 * ks + 1][1];
            uint32_t al0 = loA[2 * ks][0],     al1 = loA[2 * ks][1];
            uint32_t al2 = loA[2 * ks + 1][0], al3 = loA[2 * ks + 1][1];
            #pragma unroll
            for (int nt2 = 0; nt2 < 4; nt2++) {
                uint32_t koff = (uint32_t)((ks * 16 + (lid & 15)) * W2_STRB
                                           + (nt2 * 16 + (lid >> 4) * 8) * 2);
                uint32_t bh0, bh1, bh2, bh3, bl0, bl1, bl2, bl3;
                LDSM_X4T(bh0, bh1, bh2, bh3, sb + S_W2H + koff);
                LDSM_X4T(bl0, bl1, bl2, bl3, sb + S_W2L + koff);
                MMA16816(acc2[2 * nt2],     ah0, ah1, ah2, ah3, bh0, bh1);
                MMA16816(acc2[2 * nt2],     al0, al1, al2, al3, bh0, bh1);
                MMA16816(acc2[2 * nt2],     ah0, ah1, ah2, ah3, bl0, bl1);
                MMA16816(acc2[2 * nt2 + 1], ah0, ah1, ah2, ah3, bh2, bh3);
                MMA16816(acc2[2 * nt2 + 1], al0, al1, al2, al3, bh2, bh3);
                MMA16816(acc2[2 * nt2 + 1], ah0, ah1, ah2, ah3, bl2, bl3);
            }
        }

        // ---- store ew = acc2 + b2 into sEW ----
        #pragma unroll
        for (int nt = 0; nt < 8; nt++) {
            int r0 = rw + (lid >> 2);
            int c0 = nt * 8 + (lid & 3) * 2;
            float bb0 = sB2[c0], bb1 = sB2[c0 + 1];
            float2 v0 = {acc2[nt][0] + bb0, acc2[nt][1] + bb1};
            float2 v1 = {acc2[nt][2] + bb0, acc2[nt][3] + bb1};
            *reinterpret_cast<float2*>(sEW + r0 * EW_STR + c0) = v0;
            *reinterpret_cast<float2*>(sEW + (r0 + 8) * EW_STR + c0) = v1;
        }
        __syncthreads();

        // ---- epilogue: 16 threads/row, direct coalesced message STG ----
        {
            int q = tid & 15;                    // col group: 4 floats
            int c = q * 4;
            #pragma unroll
            for (int i = 0; i < 8; i++) {
                int r = i * 16 + (tid >> 4);
                int src = sSrc[r];
                float4 ew = *reinterpret_cast<const float4*>(sEW + r * EW_STR + c);
                float4 xv = __ldg(reinterpret_cast<const float4*>(x + (size_t)src * DI + c));
                float4 m;
                m.x = xv.x * ew.x; m.y = xv.y * ew.y;
                m.z = xv.z * ew.z; m.w = xv.w * ew.w;
                *reinterpret_cast<float4*>(g_messages + (size_t)(e0 + r) * DI + c) = m;
                float4 vv = *reinterpret_cast<const float4*>(sAV + c);
                float part = m.x * vv.x + m.y * vv.y + m.z * vv.z + m.w * vv.w;
                part += __shfl_xor_sync(0xFFFFFFFFu, part, 1);
                part += __shfl_xor_sync(0xFFFFFFFFu, part, 2);
                part += __shfl_xor_sync(0xFFFFFFFFu, part, 4);
                part += __shfl_xor_sync(0xFFFFFFFFu, part, 8);
                if (q == 0) {
                    g_scores[e0 + r] = part;
                    atomicMax(&g_segmax[sTgt[r]], enc_f(part));
                }
            }
        }
        __syncthreads();
    }
}

// ---------------- K2 ----------------
__global__ void k2_exp_denom(const int* __restrict__ ei) {
    int e = blockIdx.x * blockDim.x + threadIdx.x;
    if (e >= NE) return;
    int tgt = ei[NE + e];
    float ex = expf(g_scores[e] - dec_f(g_segmax[tgt]));
    g_ex[e] = ex;
    atomicAdd(&g_denom[tgt], ex);
}

// ---------------- K3 ----------------
__global__ void k3_scatter(const int* __restrict__ ei,
                           float* __restrict__ out, float* __restrict__ att) {
    int t = blockIdx.x * blockDim.x + threadIdx.x;
    int e = t >> 4;
    if (e >= NE) return;
    int c   = (t & 15) << 2;
    int tgt = ei[NE + e];
    float aw = g_ex[e] / g_denom[tgt];
    if ((t & 15) == 0) att[e] = aw;
    float4 m = *reinterpret_cast<const float4*>(g_messages + (size_t)e * DI + c);
    float* addr = out + (size_t)tgt * DI + c;
    float v0 = m.x * aw, v1 = m.y * aw, v2 = m.z * aw, v3 = m.w * aw;
    asm volatile("red.global.add.v4.f32 [%0], {%1, %2, %3, %4};"
                 :: "l"(addr), "f"(v0), "f"(v1), "f"(v2), "f"(v3) : "memory");
}

// ---------------- launch ----------------
extern "C" void kernel_launch(void* const* d_in, const int* in_sizes, int n_in,
                              void* d_out, int out_size) {
    const float* x  = (const float*)d_in[0];
    const int*   ei = (const int*)  d_in[1];
    const float* ea = (const float*)d_in[2];
    const float* W1 = (const float*)d_in[3];
    const float* b1 = (const float*)d_in[4];
    const float* W2 = (const float*)d_in[5];
    const float* b2 = (const float*)d_in[6];
    const float* av = (const float*)d_in[7];

    float* out = (float*)d_out;
    float* att = out + (size_t)NN * DI;

    cudaFuncSetAttribute(k1_mma, cudaFuncAttributeMaxDynamicSharedMemorySize, S_TOTAL);

    k0_init<<<(NN * DI + 255) / 256, 256>>>(out);
    k1_mma<<<148, 256, S_TOTAL>>>(x, ei, ea, W1, b1, W2, b2, av);
    k2_exp_denom<<<(NE + 255) / 256, 256>>>(ei);
    k3_scatter<<<(NE * 16 + 255) / 256, 256>>>(ei, out, att);
}

// round 8
// speedup vs baseline: 1.9106x; 1.0957x over previous
#include <cuda_runtime.h>
#include <cuda_bf16.h>
#include <cstdint>

#define NN 50000
#define NE 800000
#define DI 64
#define DE 32
#define DH 128
#define TE 128
#define NTILES (NE / TE)   // 6250

// row strides in BYTES
#define A_STRB  80     // bf16 edge tile rows
#define W1_STRB 272    // bf16 W1 rows (k-major)
#define W2_STRB 144    // bf16 W2 rows (k-major)

// ---------------- scratch ----------------
__device__ float    g_messages[(size_t)NE * DI];
__device__ float    g_scores[NE];
__device__ float    g_ex[NE];
__device__ unsigned g_segmax[NN];
__device__ float    g_denom[NN];

__device__ __forceinline__ unsigned enc_f(float f) {
    unsigned u = __float_as_uint(f);
    return (u & 0x80000000u) ? ~u : (u | 0x80000000u);
}
__device__ __forceinline__ float dec_f(unsigned u) {
    return (u & 0x80000000u) ? __uint_as_float(u & 0x7FFFFFFFu)
                             : __uint_as_float(~u);
}

__device__ __forceinline__ uint32_t smem_u32(const void* p) {
    uint32_t a;
    asm("{ .reg .u64 t; cvta.to.shared.u64 t, %1; cvt.u32.u64 %0, t; }" : "=r"(a) : "l"(p));
    return a;
}
__device__ __forceinline__ uint32_t pk2(__nv_bfloat16 a, __nv_bfloat16 b) {
    __nv_bfloat162 t; t.x = a; t.y = b;
    return *reinterpret_cast<uint32_t*>(&t);
}
__device__ __forceinline__ uint32_t pk2f(float a, float b) {
    return pk2(__float2bfloat16_rn(a), __float2bfloat16_rn(b));
}
__device__ __forceinline__ float bl(float v) {          // lo residual
    return v - __bfloat162float(__float2bfloat16_rn(v));
}
__device__ __forceinline__ float tanh_fast(float v) {
    v = fminf(fmaxf(v, -20.f), 20.f);
    float e = __expf(2.f * v);
    return 1.f - __fdividef(2.f, e + 1.f);
}

#define LDSM_X4(r0, r1, r2, r3, addr) \
    asm volatile("ldmatrix.sync.aligned.m8n8.x4.shared.b16 {%0,%1,%2,%3}, [%4];" \
        : "=r"(r0), "=r"(r1), "=r"(r2), "=r"(r3) : "r"(addr))

#define LDSM_X4T(r0, r1, r2, r3, addr) \
    asm volatile("ldmatrix.sync.aligned.m8n8.x4.trans.shared.b16 {%0,%1,%2,%3}, [%4];" \
        : "=r"(r0), "=r"(r1), "=r"(r2), "=r"(r3) : "r"(addr))

#define MMA16816(d, a0, a1, a2, a3, b0, b1) \
    asm volatile("mma.sync.aligned.m16n8k16.row.col.f32.bf16.bf16.f32 " \
        "{%0,%1,%2,%3}, {%4,%5,%6,%7}, {%8,%9}, {%0,%1,%2,%3};" \
        : "+f"((d)[0]), "+f"((d)[1]), "+f"((d)[2]), "+f"((d)[3]) \
        : "r"(a0), "r"(a1), "r"(a2), "r"(a3), "r"(b0), "r"(b1))

// ---- smem layout (bytes) ----
#define S_SRC   0
#define S_TGT   512
#define S_B1    1024
#define S_B2    1536
#define S_AV    1792
#define S_AH    2048        // 128 x 80B  = 10240
#define S_AL    12288
#define S_W1H   22528       // 32 x 272B  = 8704
#define S_W1L   31232
#define S_W2H   39936       // 128 x 144B = 18432
#define S_W2L   58368
#define S_TOTAL 76800

// ---------------- K0 ----------------
__global__ void k0_init(float* __restrict__ out) {
    int i = blockIdx.x * blockDim.x + threadIdx.x;
    if (i < NN * DI) out[i] = 0.f;
    if (i < NN) { g_segmax[i] = 0u; g_denom[i] = 0.f; }
}

// ---------------- K1: persistent mma.sync bf16x3, prefetch + reg epilogue ----------------
__global__ void __launch_bounds__(256, 1) k1_mma(
    const float* __restrict__ x,  const int*   __restrict__ ei,
    const float* __restrict__ ea, const float* __restrict__ W1,
    const float* __restrict__ b1, const float* __restrict__ W2,
    const float* __restrict__ b2, const float* __restrict__ av)
{
    extern __shared__ char smem[];
    const uint32_t sb = smem_u32(smem);
    const int tid = threadIdx.x;
    const int wid = tid >> 5;
    const int lid = tid & 31;
    const int rw  = wid * 16;            // this warp's 16 edge rows

    float* sf   = reinterpret_cast<float*>(smem);
    int*   sSrc = reinterpret_cast<int*>(smem + S_SRC);
    int*   sTgt = reinterpret_cast<int*>(smem + S_TGT);
    float* sB1  = sf + (S_B1 >> 2);
    float* sB2  = sf + (S_B2 >> 2);
    float* sAV  = sf + (S_AV >> 2);

    // ---- one-time: biases + weight hi/lo split ----
    if (tid < DH) sB1[tid] = b1[tid];
    if (tid < DI) { sB2[tid] = b2[tid]; sAV[tid] = av[tid]; }

    for (int idx = tid; idx < DE * DH; idx += 256) {            // W1 [32][128]
        int k = idx >> 7, n = idx & 127;
        float v = __ldg(W1 + k * DH + n);
        __nv_bfloat16 h = __float2bfloat16_rn(v);
        __nv_bfloat16 l = __float2bfloat16_rn(v - __bfloat162float(h));
        *reinterpret_cast<__nv_bfloat16*>(smem + S_W1H + k * W1_STRB + n * 2) = h;
        *reinterpret_cast<__nv_bfloat16*>(smem + S_W1L + k * W1_STRB + n * 2) = l;
    }
    for (int idx = tid; idx < DH * DI; idx += 256) {            // W2 [128][64]
        int k = idx >> 6, n = idx & 63;
        float v = __ldg(W2 + k * DI + n);
        __nv_bfloat16 h = __float2bfloat16_rn(v);
        __nv_bfloat16 l = __float2bfloat16_rn(v - __bfloat162float(h));
        *reinterpret_cast<__nv_bfloat16*>(smem + S_W2H + k * W2_STRB + n * 2) = h;
        *reinterpret_cast<__nv_bfloat16*>(smem + S_W2L + k * W2_STRB + n * 2) = l;
    }

    // ---- prefetch state (registers): edge tile pre-split to bf16 hi/lo ----
    uint2 pfh[4], pfl[4];
    int pfsrc = 0, pftgt = 0;

    #define LOAD_TILE(TILE) do {                                               \
        int _e0 = (TILE) * TE;                                                 \
        _Pragma("unroll")                                                      \
        for (int _i = 0; _i < 4; _i++) {                                       \
            int _idx4 = tid + _i * 256;                                        \
            int _e = _idx4 >> 3, _q = _idx4 & 7;                               \
            float4 _v = __ldg(reinterpret_cast<const float4*>(                 \
                ea + (size_t)(_e0 + _e) * DE + _q * 4));                       \
            pfh[_i] = make_uint2(pk2f(_v.x, _v.y), pk2f(_v.z, _v.w));          \
            pfl[_i] = make_uint2(pk2f(bl(_v.x), bl(_v.y)),                     \
                                 pk2f(bl(_v.z), bl(_v.w)));                    \
        }                                                                      \
        if (tid < TE) {                                                        \
            pfsrc = __ldg(ei + _e0 + tid);                                     \
            pftgt = __ldg(ei + NE + _e0 + tid);                                \
        }                                                                      \
    } while (0)

    if (blockIdx.x < NTILES) LOAD_TILE(blockIdx.x);
    __syncthreads();

    for (int tile = blockIdx.x; tile < NTILES; tile += gridDim.x) {
        const int e0 = tile * TE;

        // ---- commit prefetched tile to smem ----
        #pragma unroll
        for (int i = 0; i < 4; i++) {
            int idx4 = tid + i * 256;
            int e = idx4 >> 3, q = idx4 & 7;
            *reinterpret_cast<uint2*>(smem + S_AH + e * A_STRB + q * 8) = pfh[i];
            *reinterpret_cast<uint2*>(smem + S_AL + e * A_STRB + q * 8) = pfl[i];
        }
        if (tid < TE) { sSrc[tid] = pfsrc; sTgt[tid] = pftgt; }
        __syncthreads();

        // ---- prefetch next tile (latency hidden behind GEMMs) ----
        {
            int nxt = tile + gridDim.x;
            if (nxt < NTILES) LOAD_TILE(nxt);
        }

        // ---- GEMM1: each warp computes rows rw..rw+15 x ALL 128 cols ----
        float acc1[16][4];
        #pragma unroll
        for (int nt = 0; nt < 16; nt++)
            #pragma unroll
            for (int i = 0; i < 4; i++) acc1[nt][i] = 0.f;

        #pragma unroll
        for (int ks = 0; ks < 2; ks++) {
            uint32_t ah0, ah1, ah2, ah3, al0, al1, al2, al3;
            uint32_t aoff = (uint32_t)((rw + (lid & 15)) * A_STRB + ks * 32 + (lid >> 4) * 16);
            LDSM_X4(ah0, ah1, ah2, ah3, sb + S_AH + aoff);
            LDSM_X4(al0, al1, al2, al3, sb + S_AL + aoff);
            #pragma unroll
            for (int nt2 = 0; nt2 < 8; nt2++) {
                uint32_t koff = (uint32_t)((ks * 16 + (lid & 15)) * W1_STRB
                                           + (nt2 * 16 + (lid >> 4) * 8) * 2);
                uint32_t bh0, bh1, bh2, bh3, bl0, bl1, bl2, bl3;
                LDSM_X4T(bh0, bh1, bh2, bh3, sb + S_W1H + koff);
                LDSM_X4T(bl0, bl1, bl2, bl3, sb + S_W1L + koff);
                MMA16816(acc1[2 * nt2],     ah0, ah1, ah2, ah3, bh0, bh1);
                MMA16816(acc1[2 * nt2],     al0, al1, al2, al3, bh0, bh1);
                MMA16816(acc1[2 * nt2],     ah0, ah1, ah2, ah3, bl0, bl1);
                MMA16816(acc1[2 * nt2 + 1], ah0, ah1, ah2, ah3, bh2, bh3);
                MMA16816(acc1[2 * nt2 + 1], al0, al1, al2, al3, bh2, bh3);
                MMA16816(acc1[2 * nt2 + 1], ah0, ah1, ah2, ah3, bl2, bl3);
            }
        }

        // ---- tanh(acc1 + b1) -> bf16 hi/lo A-fragments (in registers) ----
        uint32_t hiA[16][2], loA[16][2];
        #pragma unroll
        for (int nt = 0; nt < 16; nt++) {
            int c0 = nt * 8 + (lid & 3) * 2;
            float bb0 = sB1[c0], bb1 = sB1[c0 + 1];
            float t0 = tanh_fast(acc1[nt][0] + bb0);
            float t1 = tanh_fast(acc1[nt][1] + bb1);
            float t2 = tanh_fast(acc1[nt][2] + bb0);
            float t3 = tanh_fast(acc1[nt][3] + bb1);
            hiA[nt][0] = pk2f(t0, t1);
            hiA[nt][1] = pk2f(t2, t3);
            loA[nt][0] = pk2f(bl(t0), bl(t1));
            loA[nt][1] = pk2f(bl(t2), bl(t3));
        }

        // ---- GEMM2: rows rw..rw+15 x 64 cols, A from registers ----
        float acc2[8][4];
        #pragma unroll
        for (int nt = 0; nt < 8; nt++)
            #pragma unroll
            for (int i = 0; i < 4; i++) acc2[nt][i] = 0.f;

        #pragma unroll
        for (int ks = 0; ks < 8; ks++) {
            uint32_t ah0 = hiA[2 * ks][0],     ah1 = hiA[2 * ks][1];
            uint32_t ah2 = hiA[2 * ks + 1][0], ah3 = hiA[2 * ks + 1][1];
            uint32_t al0 = loA[2 * ks][0],     al1 = loA[2 * ks][1];
            uint32_t al2 = loA[2 * ks + 1][0], al3 = loA[2 * ks + 1][1];
            #pragma unroll
            for (int nt2 = 0; nt2 < 4; nt2++) {
                uint32_t koff = (uint32_t)((ks * 16 + (lid & 15)) * W2_STRB
                                           + (nt2 * 16 + (lid >> 4) * 8) * 2);
                uint32_t bh0, bh1, bh2, bh3, bl0, bl1, bl2, bl3;
                LDSM_X4T(bh0, bh1, bh2, bh3, sb + S_W2H + koff);
                LDSM_X4T(bl0, bl1, bl2, bl3, sb + S_W2L + koff);
                MMA16816(acc2[2 * nt2],     ah0, ah1, ah2, ah3, bh0, bh1);
                MMA16816(acc2[2 * nt2],     al0, al1, al2, al3, bh0, bh1);
                MMA16816(acc2[2 * nt2],     ah0, ah1, ah2, ah3, bl0, bl1);
                MMA16816(acc2[2 * nt2 + 1], ah0, ah1, ah2, ah3, bh2, bh3);
                MMA16816(acc2[2 * nt2 + 1], al0, al1, al2, al3, bh2, bh3);
                MMA16816(acc2[2 * nt2 + 1], ah0, ah1, ah2, ah3, bl2, bl3);
            }
        }

        // ---- epilogue: direct from acc2 fragments (no smem staging) ----
        {
            const int j2 = (lid & 3) * 2;
            const int r0 = rw + (lid >> 2);
            const int r1 = r0 + 8;
            const int src0 = sSrc[r0], src1 = sSrc[r1];
            const float* x0 = x + (size_t)src0 * DI;
            const float* x1 = x + (size_t)src1 * DI;
            float* m0 = g_messages + (size_t)(e0 + r0) * DI;
            float* m1 = g_messages + (size_t)(e0 + r1) * DI;
            float p0 = 0.f, p1 = 0.f;
            #pragma unroll
            for (int nt = 0; nt < 8; nt++) {
                int c0 = nt * 8 + j2;
                float bb0 = sB2[c0], bb1 = sB2[c0 + 1];
                float vv0 = sAV[c0], vv1 = sAV[c0 + 1];
                float2 xv0 = __ldg(reinterpret_cast<const float2*>(x0 + c0));
                float2 xv1 = __ldg(reinterpret_cast<const float2*>(x1 + c0));
                float a0 = xv0.x * (acc2[nt][0] + bb0);
                float a1 = xv0.y * (acc2[nt][1] + bb1);
                float b0 = xv1.x * (acc2[nt][2] + bb0);
                float b1 = xv1.y * (acc2[nt][3] + bb1);
                *reinterpret_cast<float2*>(m0 + c0) = make_float2(a0, a1);
                *reinterpret_cast<float2*>(m1 + c0) = make_float2(b0, b1);
                p0 += a0 * vv0 + a1 * vv1;
                p1 += b0 * vv0 + b1 * vv1;
            }
            p0 += __shfl_xor_sync(0xFFFFFFFFu, p0, 1);
            p0 += __shfl_xor_sync(0xFFFFFFFFu, p0, 2);
            p1 += __shfl_xor_sync(0xFFFFFFFFu, p1, 1);
            p1 += __shfl_xor_sync(0xFFFFFFFFu, p1, 2);
            if ((lid & 3) == 0) {
                g_scores[e0 + r0] = p0;
                atomicMax(&g_segmax[sTgt[r0]], enc_f(p0));
                g_scores[e0 + r1] = p1;
                atomicMax(&g_segmax[sTgt[r1]], enc_f(p1));
            }
        }
        __syncthreads();
    }
    #undef LOAD_TILE
}

// ---------------- K2 ----------------
__global__ void k2_exp_denom(const int* __restrict__ ei) {
    int e = blockIdx.x * blockDim.x + threadIdx.x;
    if (e >= NE) return;
    int tgt = ei[NE + e];
    float ex = expf(g_scores[e] - dec_f(g_segmax[tgt]));
    g_ex[e] = ex;
    atomicAdd(&g_denom[tgt], ex);
}

// ---------------- K3 ----------------
__global__ void k3_scatter(const int* __restrict__ ei,
                           float* __restrict__ out, float* __restrict__ att) {
    int t = blockIdx.x * blockDim.x + threadIdx.x;
    int e = t >> 4;
    if (e >= NE) return;
    int c   = (t & 15) << 2;
    int tgt = ei[NE + e];
    float aw = g_ex[e] / g_denom[tgt];
    if ((t & 15) == 0) att[e] = aw;
    float4 m = *reinterpret_cast<const float4*>(g_messages + (size_t)e * DI + c);
    float* addr = out + (size_t)tgt * DI + c;
    float v0 = m.x * aw, v1 = m.y * aw, v2 = m.z * aw, v3 = m.w * aw;
    asm volatile("red.global.add.v4.f32 [%0], {%1, %2, %3, %4};"
                 :: "l"(addr), "f"(v0), "f"(v1), "f"(v2), "f"(v3) : "memory");
}

// ---------------- launch ----------------
extern "C" void kernel_launch(void* const* d_in, const int* in_sizes, int n_in,
                              void* d_out, int out_size) {
    const float* x  = (const float*)d_in[0];
    const int*   ei = (const int*)  d_in[1];
    const float* ea = (const float*)d_in[2];
    const float* W1 = (const float*)d_in[3];
    const float* b1 = (const float*)d_in[4];
    const float* W2 = (const float*)d_in[5];
    const float* b2 = (const float*)d_in[6];
    const float* av = (const float*)d_in[7];

    float* out = (float*)d_out;
    float* att = out + (size_t)NN * DI;

    cudaFuncSetAttribute(k1_mma, cudaFuncAttributeMaxDynamicSharedMemorySize, S_TOTAL);

    k0_init<<<(NN * DI + 255) / 256, 256>>>(out);
    k1_mma<<<148, 256, S_TOTAL>>>(x, ei, ea, W1, b1, W2, b2, av);
    k2_exp_denom<<<(NE + 255) / 256, 256>>>(ei);
    k3_scatter<<<(NE * 16 + 255) / 256, 256>>>(ei, out, att);
}

// round 10
// speedup vs baseline: 2.1470x; 1.1237x over previous
#include <cuda_runtime.h>
#include <cuda_bf16.h>
#include <cstdint>

#define NN 50000
#define NE 800000
#define DI 64
#define DE 32
#define DH 128
#define TE 64
#define THREADS 128
#define NTILES (NE / TE)   // 12500

// row strides in BYTES
#define A_STRB  80     // bf16 edge tile rows
#define W1_STRB 272    // bf16 W1 rows (k-major)
#define W2_STRB 144    // bf16 W2 rows (k-major)

// ---------------- scratch ----------------
__device__ float    g_messages[(size_t)NE * DI];
__device__ float    g_scores[NE];
__device__ float    g_ex[NE];
__device__ unsigned g_segmax[NN];
__device__ float    g_denom[NN];

__device__ __forceinline__ unsigned enc_f(float f) {
    unsigned u = __float_as_uint(f);
    return (u & 0x80000000u) ? ~u : (u | 0x80000000u);
}
__device__ __forceinline__ float dec_f(unsigned u) {
    return (u & 0x80000000u) ? __uint_as_float(u & 0x7FFFFFFFu)
                             : __uint_as_float(~u);
}

__device__ __forceinline__ uint32_t smem_u32(const void* p) {
    uint32_t a;
    asm("{ .reg .u64 t; cvta.to.shared.u64 t, %1; cvt.u32.u64 %0, t; }" : "=r"(a) : "l"(p));
    return a;
}
__device__ __forceinline__ uint32_t pk2(__nv_bfloat16 a, __nv_bfloat16 b) {
    __nv_bfloat162 t; t.x = a; t.y = b;
    return *reinterpret_cast<uint32_t*>(&t);
}
__device__ __forceinline__ uint32_t pk2f(float a, float b) {
    return pk2(__float2bfloat16_rn(a), __float2bfloat16_rn(b));
}
__device__ __forceinline__ float bl(float v) {          // lo residual
    return v - __bfloat162float(__float2bfloat16_rn(v));
}
__device__ __forceinline__ float tanh_fast(float v) {
    v = fminf(fmaxf(v, -20.f), 20.f);
    float e = __expf(2.f * v);
    return 1.f - __fdividef(2.f, e + 1.f);
}

#define LDSM_X4(r0, r1, r2, r3, addr) \
    asm volatile("ldmatrix.sync.aligned.m8n8.x4.shared.b16 {%0,%1,%2,%3}, [%4];" \
        : "=r"(r0), "=r"(r1), "=r"(r2), "=r"(r3) : "r"(addr))

#define LDSM_X4T(r0, r1, r2, r3, addr) \
    asm volatile("ldmatrix.sync.aligned.m8n8.x4.trans.shared.b16 {%0,%1,%2,%3}, [%4];" \
        : "=r"(r0), "=r"(r1), "=r"(r2), "=r"(r3) : "r"(addr))

#define MMA16816(d, a0, a1, a2, a3, b0, b1) \
    asm volatile("mma.sync.aligned.m16n8k16.row.col.f32.bf16.bf16.f32 " \
        "{%0,%1,%2,%3}, {%4,%5,%6,%7}, {%8,%9}, {%0,%1,%2,%3};" \
        : "+f"((d)[0]), "+f"((d)[1]), "+f"((d)[2]), "+f"((d)[3]) \
        : "r"(a0), "r"(a1), "r"(a2), "r"(a3), "r"(b0), "r"(b1))

// ---- smem layout (bytes) ----
#define S_SRC   0           // 64 ints
#define S_TGT   256
#define S_B1    512         // 128 f
#define S_B2    1024        // 64 f
#define S_AV    1280
#define S_AH    1536        // 64 x 80B = 5120
#define S_AL    6656
#define S_W1H   11776       // 32 x 272B = 8704
#define S_W1L   20480
#define S_W2H   29184       // 128 x 144B = 18432
#define S_W2L   47616
#define S_TOTAL 66048

// ---------------- K0 ----------------
__global__ void k0_init(float* __restrict__ out) {
    int i = blockIdx.x * blockDim.x + threadIdx.x;
    if (i < NN * DI) out[i] = 0.f;
    if (i < NN) { g_segmax[i] = 0u; g_denom[i] = 0.f; }
}

// ---------------- K1: persistent mma.sync bf16x3, 2 CTAs/SM ----------------
__global__ void __launch_bounds__(THREADS, 2) k1_mma(
    const float* __restrict__ x,  const int*   __restrict__ ei,
    const float* __restrict__ ea, const float* __restrict__ W1,
    const float* __restrict__ b1, const float* __restrict__ W2,
    const float* __restrict__ b2, const float* __restrict__ av)
{
    extern __shared__ char smem[];
    const uint32_t sb = smem_u32(smem);
    const int tid = threadIdx.x;
    const int wid = tid >> 5;
    const int lid = tid & 31;
    const int rw  = wid * 16;            // this warp's 16 edge rows (of 64)

    float* sf   = reinterpret_cast<float*>(smem);
    int*   sSrc = reinterpret_cast<int*>(smem + S_SRC);
    int*   sTgt = reinterpret_cast<int*>(smem + S_TGT);
    float* sB1  = sf + (S_B1 >> 2);
    float* sB2  = sf + (S_B2 >> 2);
    float* sAV  = sf + (S_AV >> 2);

    // ---- one-time: biases + weight hi/lo split ----
    if (tid < DH) sB1[tid] = b1[tid];
    if (tid < DI) { sB2[tid] = b2[tid]; sAV[tid] = av[tid]; }

    for (int idx = tid; idx < DE * DH; idx += THREADS) {        // W1 [32][128]
        int k = idx >> 7, n = idx & 127;
        float v = __ldg(W1 + k * DH + n);
        __nv_bfloat16 h = __float2bfloat16_rn(v);
        __nv_bfloat16 l = __float2bfloat16_rn(v - __bfloat162float(h));
        *reinterpret_cast<__nv_bfloat16*>(smem + S_W1H + k * W1_STRB + n * 2) = h;
        *reinterpret_cast<__nv_bfloat16*>(smem + S_W1L + k * W1_STRB + n * 2) = l;
    }
    for (int idx = tid; idx < DH * DI; idx += THREADS) {        // W2 [128][64]
        int k = idx >> 6, n = idx & 63;
        float v = __ldg(W2 + k * DI + n);
        __nv_bfloat16 h = __float2bfloat16_rn(v);
        __nv_bfloat16 l = __float2bfloat16_rn(v - __bfloat162float(h));
        *reinterpret_cast<__nv_bfloat16*>(smem + S_W2H + k * W2_STRB + n * 2) = h;
        *reinterpret_cast<__nv_bfloat16*>(smem + S_W2L + k * W2_STRB + n * 2) = l;
    }

    // ---- prefetch state (registers): edge tile pre-split to bf16 hi/lo ----
    uint2 pfh[4], pfl[4];
    int pfsrc = 0, pftgt = 0;

    #define LOAD_TILE(TILE) do {                                               \
        int _e0 = (TILE) * TE;                                                 \
        _Pragma("unroll")                                                      \
        for (int _i = 0; _i < 4; _i++) {                                       \
            int _idx4 = tid + _i * THREADS;                                    \
            int _e = _idx4 >> 3, _q = _idx4 & 7;                               \
            float4 _v = __ldg(reinterpret_cast<const float4*>(                 \
                ea + (size_t)(_e0 + _e) * DE + _q * 4));                       \
            pfh[_i] = make_uint2(pk2f(_v.x, _v.y), pk2f(_v.z, _v.w));          \
            pfl[_i] = make_uint2(pk2f(bl(_v.x), bl(_v.y)),                     \
                                 pk2f(bl(_v.z), bl(_v.w)));                    \
        }                                                                      \
        if (tid < TE) {                                                        \
            pfsrc = __ldg(ei + _e0 + tid);                                     \
            pftgt = __ldg(ei + NE + _e0 + tid);                                \
        }                                                                      \
    } while (0)

    if (blockIdx.x < NTILES) LOAD_TILE(blockIdx.x);
    __syncthreads();

    for (int tile = blockIdx.x; tile < NTILES; tile += gridDim.x) {
        const int e0 = tile * TE;

        // ---- commit prefetched tile to smem ----
        #pragma unroll
        for (int i = 0; i < 4; i++) {
            int idx4 = tid + i * THREADS;
            int e = idx4 >> 3, q = idx4 & 7;
            *reinterpret_cast<uint2*>(smem + S_AH + e * A_STRB + q * 8) = pfh[i];
            *reinterpret_cast<uint2*>(smem + S_AL + e * A_STRB + q * 8) = pfl[i];
        }
        if (tid < TE) { sSrc[tid] = pfsrc; sTgt[tid] = pftgt; }
        __syncthreads();

        // ---- prefetch next tile (latency hidden behind GEMMs) ----
        {
            int nxt = tile + gridDim.x;
            if (nxt < NTILES) LOAD_TILE(nxt);
        }

        // ---- GEMM1: warp computes rows rw..rw+15 x ALL 128 cols ----
        float acc1[16][4];
        #pragma unroll
        for (int nt = 0; nt < 16; nt++)
            #pragma unroll
            for (int i = 0; i < 4; i++) acc1[nt][i] = 0.f;

        #pragma unroll
        for (int ks = 0; ks < 2; ks++) {
            uint32_t ah0, ah1, ah2, ah3, al0, al1, al2, al3;
            uint32_t aoff = (uint32_t)((rw + (lid & 15)) * A_STRB + ks * 32 + (lid >> 4) * 16);
            LDSM_X4(ah0, ah1, ah2, ah3, sb + S_AH + aoff);
            LDSM_X4(al0, al1, al2, al3, sb + S_AL + aoff);
            #pragma unroll
            for (int nt2 = 0; nt2 < 8; nt2++) {
                uint32_t koff = (uint32_t)((ks * 16 + (lid & 15)) * W1_STRB
                                           + (nt2 * 16 + (lid >> 4) * 8) * 2);
                uint32_t bh0, bh1, bh2, bh3, bl0, bl1, bl2, bl3;
                LDSM_X4T(bh0, bh1, bh2, bh3, sb + S_W1H + koff);
                LDSM_X4T(bl0, bl1, bl2, bl3, sb + S_W1L + koff);
                MMA16816(acc1[2 * nt2],     ah0, ah1, ah2, ah3, bh0, bh1);
                MMA16816(acc1[2 * nt2],     al0, al1, al2, al3, bh0, bh1);
                MMA16816(acc1[2 * nt2],     ah0, ah1, ah2, ah3, bl0, bl1);
                MMA16816(acc1[2 * nt2 + 1], ah0, ah1, ah2, ah3, bh2, bh3);
                MMA16816(acc1[2 * nt2 + 1], al0, al1, al2, al3, bh2, bh3);
                MMA16816(acc1[2 * nt2 + 1], ah0, ah1, ah2, ah3, bl2, bl3);
            }
        }

        // ---- tanh(acc1 + b1) -> bf16 hi/lo A-fragments (in registers) ----
        uint32_t hiA[16][2], loA[16][2];
        #pragma unroll
        for (int nt = 0; nt < 16; nt++) {
            int c0 = nt * 8 + (lid & 3) * 2;
            float bb0 = sB1[c0], bb1 = sB1[c0 + 1];
            float t0 = tanh_fast(acc1[nt][0] + bb0);
            float t1 = tanh_fast(acc1[nt][1] + bb1);
            float t2 = tanh_fast(acc1[nt][2] + bb0);
            float t3 = tanh_fast(acc1[nt][3] + bb1);
            hiA[nt][0] = pk2f(t0, t1);
            hiA[nt][1] = pk2f(t2, t3);
            loA[nt][0] = pk2f(bl(t0), bl(t1));
            loA[nt][1] = pk2f(bl(t2), bl(t3));
        }

        // ---- GEMM2: rows rw..rw+15 x 64 cols, A from registers ----
        float acc2[8][4];
        #pragma unroll
        for (int nt = 0; nt < 8; nt++)
            #pragma unroll
            for (int i = 0; i < 4; i++) acc2[nt][i] = 0.f;

        #pragma unroll
        for (int ks = 0; ks < 8; ks++) {
            uint32_t ah0 = hiA[2 * ks][0],     ah1 = hiA[2 * ks][1];
            uint32_t ah2 = hiA[2 * ks + 1][0], ah3 = hiA[2 * ks + 1][1];
            uint32_t al0 = loA[2 * ks][0],     al1 = loA[2 * ks][1];
            uint32_t al2 = loA[2 * ks + 1][0], al3 = loA[2 * ks + 1][1];
            #pragma unroll
            for (int nt2 = 0; nt2 < 4; nt2++) {
                uint32_t koff = (uint32_t)((ks * 16 + (lid & 15)) * W2_STRB
                                           + (nt2 * 16 + (lid >> 4) * 8) * 2);
                uint32_t bh0, bh1, bh2, bh3, bl0, bl1, bl2, bl3;
                LDSM_X4T(bh0, bh1, bh2, bh3, sb + S_W2H + koff);
                LDSM_X4T(bl0, bl1, bl2, bl3, sb + S_W2L + koff);
                MMA16816(acc2[2 * nt2],     ah0, ah1, ah2, ah3, bh0, bh1);
                MMA16816(acc2[2 * nt2],     al0, al1, al2, al3, bh0, bh1);
                MMA16816(acc2[2 * nt2],     ah0, ah1, ah2, ah3, bl0, bl1);
                MMA16816(acc2[2 * nt2 + 1], ah0, ah1, ah2, ah3, bh2, bh3);
                MMA16816(acc2[2 * nt2 + 1], al0, al1, al2, al3, bh2, bh3);
                MMA16816(acc2[2 * nt2 + 1], ah0, ah1, ah2, ah3, bl2, bl3);
            }
        }

        // ---- epilogue: direct from acc2 fragments (no smem staging) ----
        {
            const int j2 = (lid & 3) * 2;
            const int r0 = rw + (lid >> 2);
            const int r1 = r0 + 8;
            const int src0 = sSrc[r0], src1 = sSrc[r1];
            const float* x0 = x + (size_t)src0 * DI;
            const float* x1 = x + (size_t)src1 * DI;
            float* m0 = g_messages + (size_t)(e0 + r0) * DI;
            float* m1 = g_messages + (size_t)(e0 + r1) * DI;
            float p0 = 0.f, p1 = 0.f;
            #pragma unroll
            for (int nt = 0; nt < 8; nt++) {
                int c0 = nt * 8 + j2;
                float bb0 = sB2[c0], bb1 = sB2[c0 + 1];
                float vv0 = sAV[c0], vv1 = sAV[c0 + 1];
                float2 xv0 = __ldg(reinterpret_cast<const float2*>(x0 + c0));
                float2 xv1 = __ldg(reinterpret_cast<const float2*>(x1 + c0));
                float a0 = xv0.x * (acc2[nt][0] + bb0);
                float a1 = xv0.y * (acc2[nt][1] + bb1);
                float b0 = xv1.x * (acc2[nt][2] + bb0);
                float b1 = xv1.y * (acc2[nt][3] + bb1);
                *reinterpret_cast<float2*>(m0 + c0) = make_float2(a0, a1);
                *reinterpret_cast<float2*>(m1 + c0) = make_float2(b0, b1);
                p0 += a0 * vv0 + a1 * vv1;
                p1 += b0 * vv0 + b1 * vv1;
            }
            p0 += __shfl_xor_sync(0xFFFFFFFFu, p0, 1);
            p0 += __shfl_xor_sync(0xFFFFFFFFu, p0, 2);
            p1 += __shfl_xor_sync(0xFFFFFFFFu, p1, 1);
            p1 += __shfl_xor_sync(0xFFFFFFFFu, p1, 2);
            if ((lid & 3) == 0) {
                g_scores[e0 + r0] = p0;
                atomicMax(&g_segmax[sTgt[r0]], enc_f(p0));
                g_scores[e0 + r1] = p1;
                atomicMax(&g_segmax[sTgt[r1]], enc_f(p1));
            }
        }
        __syncthreads();
    }
    #undef LOAD_TILE
}

// ---------------- K2 ----------------
__global__ void k2_exp_denom(const int* __restrict__ ei) {
    int e = blockIdx.x * blockDim.x + threadIdx.x;
    if (e >= NE) return;
    int tgt = ei[NE + e];
    float ex = expf(g_scores[e] - dec_f(g_segmax[tgt]));
    g_ex[e] = ex;
    atomicAdd(&g_denom[tgt], ex);
}

// ---------------- K3 ----------------
__global__ void k3_scatter(const int* __restrict__ ei,
                           float* __restrict__ out, float* __restrict__ att) {
    int t = blockIdx.x * blockDim.x + threadIdx.x;
    int e = t >> 4;
    if (e >= NE) return;
    int c   = (t & 15) << 2;
    int tgt = ei[NE + e];
    float aw = g_ex[e] / g_denom[tgt];
    if ((t & 15) == 0) att[e] = aw;
    float4 m = *reinterpret_cast<const float4*>(g_messages + (size_t)e * DI + c);
    float* addr = out + (size_t)tgt * DI + c;
    float v0 = m.x * aw, v1 = m.y * aw, v2 = m.z * aw, v3 = m.w * aw;
    asm volatile("red.global.add.v4.f32 [%0], {%1, %2, %3, %4};"
                 :: "l"(addr), "f"(v0), "f"(v1), "f"(v2), "f"(v3) : "memory");
}

// ---------------- launch ----------------
extern "C" void kernel_launch(void* const* d_in, const int* in_sizes, int n_in,
                              void* d_out, int out_size) {
    const float* x  = (const float*)d_in[0];
    const int*   ei = (const int*)  d_in[1];
    const float* ea = (const float*)d_in[2];
    const float* W1 = (const float*)d_in[3];
    const float* b1 = (const float*)d_in[4];
    const float* W2 = (const float*)d_in[5];
    const float* b2 = (const float*)d_in[6];
    const float* av = (const float*)d_in[7];

    float* out = (float*)d_out;
    float* att = out + (size_t)NN * DI;

    cudaFuncSetAttribute(k1_mma, cudaFuncAttributeMaxDynamicSharedMemorySize, S_TOTAL);

    k0_init<<<(NN * DI + 255) / 256, 256>>>(out);
    k1_mma<<<296, THREADS, S_TOTAL>>>(x, ei, ea, W1, b1, W2, b2, av);
    k2_exp_denom<<<(NE + 255) / 256, 256>>>(ei);
    k3_scatter<<<(NE * 16 + 255) / 256, 256>>>(ei, out, att);
}

// round 12
// speedup vs baseline: 2.1918x; 1.0208x over previous
#include <cuda_runtime.h>
#include <cuda_bf16.h>
#include <cuda_fp16.h>
#include <cstdint>

#define NN 50000
#define NE 800000
#define DI 64
#define DE 32
#define DH 128
#define TE 64
#define THREADS 128
#define NTILES (NE / TE)   // 12500

// row strides in BYTES
#define A_STRB  80     // bf16 edge tile rows
#define W1_STRB 272    // bf16 W1 rows (k-major)
#define W2_STRB 144    // bf16 W2 rows (k-major)

// ---------------- scratch ----------------
__device__ __half   g_msg[(size_t)NE * DI];   // fp16 messages, 102 MB
__device__ float    g_scores[NE];
__device__ float    g_ex[NE];
__device__ unsigned g_segmax[NN];
__device__ float    g_denom[NN];

__device__ __forceinline__ unsigned enc_f(float f) {
    unsigned u = __float_as_uint(f);
    return (u & 0x80000000u) ? ~u : (u | 0x80000000u);
}
__device__ __forceinline__ float dec_f(unsigned u) {
    return (u & 0x80000000u) ? __uint_as_float(u & 0x7FFFFFFFu)
                             : __uint_as_float(~u);
}

__device__ __forceinline__ uint32_t smem_u32(const void* p) {
    uint32_t a;
    asm("{ .reg .u64 t; cvta.to.shared.u64 t, %1; cvt.u32.u64 %0, t; }" : "=r"(a) : "l"(p));
    return a;
}
__device__ __forceinline__ uint32_t pk2(__nv_bfloat16 a, __nv_bfloat16 b) {
    __nv_bfloat162 t; t.x = a; t.y = b;
    return *reinterpret_cast<uint32_t*>(&t);
}
__device__ __forceinline__ uint32_t pk2f(float a, float b) {
    return pk2(__float2bfloat16_rn(a), __float2bfloat16_rn(b));
}
__device__ __forceinline__ float bl(float v) {          // lo residual
    return v - __bfloat162float(__float2bfloat16_rn(v));
}
__device__ __forceinline__ float tanh_fast(float v) {
    v = fminf(fmaxf(v, -20.f), 20.f);
    float e = __expf(2.f * v);
    return 1.f - __fdividef(2.f, e + 1.f);
}

#define LDSM_X4(r0, r1, r2, r3, addr) \
    asm volatile("ldmatrix.sync.aligned.m8n8.x4.shared.b16 {%0,%1,%2,%3}, [%4];" \
        : "=r"(r0), "=r"(r1), "=r"(r2), "=r"(r3) : "r"(addr))

#define LDSM_X4T(r0, r1, r2, r3, addr) \
    asm volatile("ldmatrix.sync.aligned.m8n8.x4.trans.shared.b16 {%0,%1,%2,%3}, [%4];" \
        : "=r"(r0), "=r"(r1), "=r"(r2), "=r"(r3) : "r"(addr))

#define MMA16816(d, a0, a1, a2, a3, b0, b1) \
    asm volatile("mma.sync.aligned.m16n8k16.row.col.f32.bf16.bf16.f32 " \
        "{%0,%1,%2,%3}, {%4,%5,%6,%7}, {%8,%9}, {%0,%1,%2,%3};" \
        : "+f"((d)[0]), "+f"((d)[1]), "+f"((d)[2]), "+f"((d)[3]) \
        : "r"(a0), "r"(a1), "r"(a2), "r"(a3), "r"(b0), "r"(b1))

// ---- smem layout (bytes) ----
#define S_SRC   0           // 64 ints
#define S_TGT   256
#define S_B1    512         // 128 f
#define S_B2    1024        // 64 f
#define S_AV    1280
#define S_AH    1536        // 64 x 80B = 5120
#define S_AL    6656
#define S_W1H   11776       // 32 x 272B = 8704
#define S_W1L   20480
#define S_W2H   29184       // 128 x 144B = 18432
#define S_W2L   47616
#define S_TOTAL 66048

// ---------------- K0 ----------------
__global__ void k0_init(float* __restrict__ out) {
    int i = blockIdx.x * blockDim.x + threadIdx.x;
    if (i < NN * DI) out[i] = 0.f;
    if (i < NN) { g_segmax[i] = 0u; g_denom[i] = 0.f; }
}

// ---------------- K1: persistent mma.sync bf16x3, 2 CTAs/SM, fp16 msg ----------------
__global__ void __launch_bounds__(THREADS, 2) k1_mma(
    const float* __restrict__ x,  const int*   __restrict__ ei,
    const float* __restrict__ ea, const float* __restrict__ W1,
    const float* __restrict__ b1, const float* __restrict__ W2,
    const float* __restrict__ b2, const float* __restrict__ av)
{
    extern __shared__ char smem[];
    const uint32_t sb = smem_u32(smem);
    const int tid = threadIdx.x;
    const int wid = tid >> 5;
    const int lid = tid & 31;
    const int rw  = wid * 16;            // this warp's 16 edge rows (of 64)

    float* sf   = reinterpret_cast<float*>(smem);
    int*   sSrc = reinterpret_cast<int*>(smem + S_SRC);
    int*   sTgt = reinterpret_cast<int*>(smem + S_TGT);
    float* sB1  = sf + (S_B1 >> 2);
    float* sB2  = sf + (S_B2 >> 2);
    float* sAV  = sf + (S_AV >> 2);

    // ---- one-time: biases + weight hi/lo split ----
    if (tid < DH) sB1[tid] = b1[tid];
    if (tid < DI) { sB2[tid] = b2[tid]; sAV[tid] = av[tid]; }

    for (int idx = tid; idx < DE * DH; idx += THREADS) {        // W1 [32][128]
        int k = idx >> 7, n = idx & 127;
        float v = __ldg(W1 + k * DH + n);
        __nv_bfloat16 h = __float2bfloat16_rn(v);
        __nv_bfloat16 l = __float2bfloat16_rn(v - __bfloat162float(h));
        *reinterpret_cast<__nv_bfloat16*>(smem + S_W1H + k * W1_STRB + n * 2) = h;
        *reinterpret_cast<__nv_bfloat16*>(smem + S_W1L + k * W1_STRB + n * 2) = l;
    }
    for (int idx = tid; idx < DH * DI; idx += THREADS) {        // W2 [128][64]
        int k = idx >> 6, n = idx & 63;
        float v = __ldg(W2 + k * DI + n);
        __nv_bfloat16 h = __float2bfloat16_rn(v);
        __nv_bfloat16 l = __float2bfloat16_rn(v - __bfloat162float(h));
        *reinterpret_cast<__nv_bfloat16*>(smem + S_W2H + k * W2_STRB + n * 2) = h;
        *reinterpret_cast<__nv_bfloat16*>(smem + S_W2L + k * W2_STRB + n * 2) = l;
    }

    // ---- prefetch state (registers): edge tile pre-split to bf16 hi/lo ----
    uint2 pfh[4], pfl[4];
    int pfsrc = 0, pftgt = 0;

    #define LOAD_TILE(TILE) do {                                               \
        int _e0 = (TILE) * TE;                                                 \
        _Pragma("unroll")                                                      \
        for (int _i = 0; _i < 4; _i++) {                                       \
            int _idx4 = tid + _i * THREADS;                                    \
            int _e = _idx4 >> 3, _q = _idx4 & 7;                               \
            float4 _v = __ldg(reinterpret_cast<const float4*>(                 \
                ea + (size_t)(_e0 + _e) * DE + _q * 4));                       \
            pfh[_i] = make_uint2(pk2f(_v.x, _v.y), pk2f(_v.z, _v.w));          \
            pfl[_i] = make_uint2(pk2f(bl(_v.x), bl(_v.y)),                     \
                                 pk2f(bl(_v.z), bl(_v.w)));                    \
        }                                                                      \
        if (tid < TE) {                                                        \
            pfsrc = __ldg(ei + _e0 + tid);                                     \
            pftgt = __ldg(ei + NE + _e0 + tid);                                \
        }                                                                      \
    } while (0)

    if (blockIdx.x < NTILES) LOAD_TILE(blockIdx.x);
    __syncthreads();

    for (int tile = blockIdx.x; tile < NTILES; tile += gridDim.x) {
        const int e0 = tile * TE;

        // ---- commit prefetched tile to smem ----
        #pragma unroll
        for (int i = 0; i < 4; i++) {
            int idx4 = tid + i * THREADS;
            int e = idx4 >> 3, q = idx4 & 7;
            *reinterpret_cast<uint2*>(smem + S_AH + e * A_STRB + q * 8) = pfh[i];
            *reinterpret_cast<uint2*>(smem + S_AL + e * A_STRB + q * 8) = pfl[i];
        }
        if (tid < TE) { sSrc[tid] = pfsrc; sTgt[tid] = pftgt; }
        __syncthreads();

        // ---- prefetch next tile (latency hidden behind GEMMs) ----
        {
            int nxt = tile + gridDim.x;
            if (nxt < NTILES) LOAD_TILE(nxt);
        }

        // ---- GEMM1: warp computes rows rw..rw+15 x ALL 128 cols ----
        float acc1[16][4];
        #pragma unroll
        for (int nt = 0; nt < 16; nt++)
            #pragma unroll
            for (int i = 0; i < 4; i++) acc1[nt][i] = 0.f;

        #pragma unroll
        for (int ks = 0; ks < 2; ks++) {
            uint32_t ah0, ah1, ah2, ah3, al0, al1, al2, al3;
            uint32_t aoff = (uint32_t)((rw + (lid & 15)) * A_STRB + ks * 32 + (lid >> 4) * 16);
            LDSM_X4(ah0, ah1, ah2, ah3, sb + S_AH + aoff);
            LDSM_X4(al0, al1, al2, al3, sb + S_AL + aoff);
            #pragma unroll
            for (int nt2 = 0; nt2 < 8; nt2++) {
                uint32_t koff = (uint32_t)((ks * 16 + (lid & 15)) * W1_STRB
                                           + (nt2 * 16 + (lid >> 4) * 8) * 2);
                uint32_t bh0, bh1, bh2, bh3, bl0, bl1, bl2, bl3;
                LDSM_X4T(bh0, bh1, bh2, bh3, sb + S_W1H + koff);
                LDSM_X4T(bl0, bl1, bl2, bl3, sb + S_W1L + koff);
                MMA16816(acc1[2 * nt2],     ah0, ah1, ah2, ah3, bh0, bh1);
                MMA16816(acc1[2 * nt2],     al0, al1, al2, al3, bh0, bh1);
                MMA16816(acc1[2 * nt2],     ah0, ah1, ah2, ah3, bl0, bl1);
                MMA16816(acc1[2 * nt2 + 1], ah0, ah1, ah2, ah3, bh2, bh3);
                MMA16816(acc1[2 * nt2 + 1], al0, al1, al2, al3, bh2, bh3);
                MMA16816(acc1[2 * nt2 + 1], ah0, ah1, ah2, ah3, bl2, bl3);
            }
        }

        // ---- tanh(acc1 + b1) -> bf16 hi/lo A-fragments (in registers) ----
        uint32_t hiA[16][2], loA[16][2];
        #pragma unroll
        for (int nt = 0; nt < 16; nt++) {
            int c0 = nt * 8 + (lid & 3) * 2;
            float bb0 = sB1[c0], bb1 = sB1[c0 + 1];
            float t0 = tanh_fast(acc1[nt][0] + bb0);
            float t1 = tanh_fast(acc1[nt][1] + bb1);
            float t2 = tanh_fast(acc1[nt][2] + bb0);
            float t3 = tanh_fast(acc1[nt][3] + bb1);
            hiA[nt][0] = pk2f(t0, t1);
            hiA[nt][1] = pk2f(t2, t3);
            loA[nt][0] = pk2f(bl(t0), bl(t1));
            loA[nt][1] = pk2f(bl(t2), bl(t3));
        }

        // ---- GEMM2: rows rw..rw+15 x 64 cols, A from registers ----
        float acc2[8][4];
        #pragma unroll
        for (int nt = 0; nt < 8; nt++)
            #pragma unroll
            for (int i = 0; i < 4; i++) acc2[nt][i] = 0.f;

        #pragma unroll
        for (int ks = 0; ks < 8; ks++) {
            uint32_t ah0 = hiA[2 * ks][0],     ah1 = hiA[2 * ks][1];
            uint32_t ah2 = hiA[2 * ks + 1][0], ah3 = hiA[2 * ks + 1][1];
            uint32_t al0 = loA[2 * ks][0],     al1 = loA[2 * ks][1];
            uint32_t al2 = loA[2 * ks + 1][0], al3 = loA[2 * ks + 1][1];
            #pragma unroll
            for (int nt2 = 0; nt2 < 4; nt2++) {
                uint32_t koff = (uint32_t)((ks * 16 + (lid & 15)) * W2_STRB
                                           + (nt2 * 16 + (lid >> 4) * 8) * 2);
                uint32_t bh0, bh1, bh2, bh3, bl0, bl1, bl2, bl3;
                LDSM_X4T(bh0, bh1, bh2, bh3, sb + S_W2H + koff);
                LDSM_X4T(bl0, bl1, bl2, bl3, sb + S_W2L + koff);
                MMA16816(acc2[2 * nt2],     ah0, ah1, ah2, ah3, bh0, bh1);
                MMA16816(acc2[2 * nt2],     al0, al1, al2, al3, bh0, bh1);
                MMA16816(acc2[2 * nt2],     ah0, ah1, ah2, ah3, bl0, bl1);
                MMA16816(acc2[2 * nt2 + 1], ah0, ah1, ah2, ah3, bh2, bh3);
                MMA16816(acc2[2 * nt2 + 1], al0, al1, al2, al3, bh2, bh3);
                MMA16816(acc2[2 * nt2 + 1], ah0, ah1, ah2, ah3, bl2, bl3);
            }
        }

        // ---- epilogue: direct from acc2 fragments; fp16 streaming msg store ----
        {
            const int j2 = (lid & 3) * 2;
            const int r0 = rw + (lid >> 2);
            const int r1 = r0 + 8;
            const int src0 = sSrc[r0], src1 = sSrc[r1];
            const float* x0 = x + (size_t)src0 * DI;
            const float* x1 = x + (size_t)src1 * DI;
            __half2* m0 = reinterpret_cast<__half2*>(g_msg + (size_t)(e0 + r0) * DI);
            __half2* m1 = reinterpret_cast<__half2*>(g_msg + (size_t)(e0 + r1) * DI);
            float p0 = 0.f, p1 = 0.f;
            #pragma unroll
            for (int nt = 0; nt < 8; nt++) {
                int c0 = nt * 8 + j2;
                float bb0 = sB2[c0], bb1 = sB2[c0 + 1];
                float vv0 = sAV[c0], vv1 = sAV[c0 + 1];
                float2 xv0 = __ldg(reinterpret_cast<const float2*>(x0 + c0));
                float2 xv1 = __ldg(reinterpret_cast<const float2*>(x1 + c0));
                float a0 = xv0.x * (acc2[nt][0] + bb0);
                float a1 = xv0.y * (acc2[nt][1] + bb1);
                float b0 = xv1.x * (acc2[nt][2] + bb0);
                float b1 = xv1.y * (acc2[nt][3] + bb1);
                __stcs(m0 + (c0 >> 1), __floats2half2_rn(a0, a1));
                __stcs(m1 + (c0 >> 1), __floats2half2_rn(b0, b1));
                p0 += a0 * vv0 + a1 * vv1;
                p1 += b0 * vv0 + b1 * vv1;
            }
            p0 += __shfl_xor_sync(0xFFFFFFFFu, p0, 1);
            p0 += __shfl_xor_sync(0xFFFFFFFFu, p0, 2);
            p1 += __shfl_xor_sync(0xFFFFFFFFu, p1, 1);
            p1 += __shfl_xor_sync(0xFFFFFFFFu, p1, 2);
            if ((lid & 3) == 0) {
                g_scores[e0 + r0] = p0;
                atomicMax(&g_segmax[sTgt[r0]], enc_f(p0));
                g_scores[e0 + r1] = p1;
                atomicMax(&g_segmax[sTgt[r1]], enc_f(p1));
            }
        }
        __syncthreads();
    }
    #undef LOAD_TILE
}

// ---------------- K2 ----------------
__global__ void k2_exp_denom(const int* __restrict__ ei) {
    int e = blockIdx.x * blockDim.x + threadIdx.x;
    if (e >= NE) return;
    int tgt = ei[NE + e];
    float ex = expf(g_scores[e] - dec_f(g_segmax[tgt]));
    g_ex[e] = ex;
    atomicAdd(&g_denom[tgt], ex);
}

// ---------------- K3: 8 threads/edge, fp16 msg read, v4 reductions ----------------
__global__ void k3_scatter(const int* __restrict__ ei,
                           float* __restrict__ out, float* __restrict__ att) {
    int t = blockIdx.x * blockDim.x + threadIdx.x;
    int e = t >> 3;
    if (e >= NE) return;
    int q   = t & 7;                     // 8 halves per thread
    int tgt = ei[NE + e];
    float aw = g_ex[e] / g_denom[tgt];
    if (q == 0) att[e] = aw;
    const uint4 mv = __ldcs(reinterpret_cast<const uint4*>(g_msg + (size_t)e * DI) + q);
    const __half2* hp = reinterpret_cast<const __half2*>(&mv);
    float2 f0 = __half22float2(hp[0]);
    float2 f1 = __half22float2(hp[1]);
    float2 f2 = __half22float2(hp[2]);
    float2 f3 = __half22float2(hp[3]);
    float* addr = out + (size_t)tgt * DI + q * 8;
    asm volatile("red.global.add.v4.f32 [%0], {%1, %2, %3, %4};"
                 :: "l"(addr), "f"(f0.x * aw), "f"(f0.y * aw),
                    "f"(f1.x * aw), "f"(f1.y * aw) : "memory");
    asm volatile("red.global.add.v4.f32 [%0], {%1, %2, %3, %4};"
                 :: "l"(addr + 4), "f"(f2.x * aw), "f"(f2.y * aw),
                    "f"(f3.x * aw), "f"(f3.y * aw) : "memory");
}

// ---------------- launch ----------------
extern "C" void kernel_launch(void* const* d_in, const int* in_sizes, int n_in,
                              void* d_out, int out_size) {
    const float* x  = (const float*)d_in[0];
    const int*   ei = (const int*)  d_in[1];
    const float* ea = (const float*)d_in[2];
    const float* W1 = (const float*)d_in[3];
    const float* b1 = (const float*)d_in[4];
    const float* W2 = (const float*)d_in[5];
    const float* b2 = (const float*)d_in[6];
    const float* av = (const float*)d_in[7];

    float* out = (float*)d_out;
    float* att = out + (size_t)NN * DI;

    cudaFuncSetAttribute(k1_mma, cudaFuncAttributeMaxDynamicSharedMemorySize, S_TOTAL);

    k0_init<<<(NN * DI + 255) / 256, 256>>>(out);
    k1_mma<<<296, THREADS, S_TOTAL>>>(x, ei, ea, W1, b1, W2, b2, av);
    k2_exp_denom<<<(NE + 255) / 256, 256>>>(ei);
    k3_scatter<<<(NE * 8 + 255) / 256, 256>>>(ei, out, att);
}